// round 1
// baseline (speedup 1.0000x reference)
#include <cuda_runtime.h>
#include <math.h>

#define N_NODES  100000
#define N_EDGES  1600000
#define N_GRAPHS 1000
#define D        128

// ---------------- scratch (static device globals; no allocation) ----------------
__device__ float g_h  [(size_t)N_NODES * D];   // current activations
__device__ float g_hs [(size_t)N_NODES * D];   // (h @ W) * dinv[row]
__device__ float g_acc[(size_t)N_NODES * D];   // edge-aggregation accumulator
__device__ float g_dinv[N_NODES];
__device__ int   g_deg [N_NODES];
__device__ float g_gmax[N_GRAPHS * D];

// ---------------- degree + normalization ----------------
__global__ void k_count_deg(const int* __restrict__ dst) {
    int e = blockIdx.x * blockDim.x + threadIdx.x;
    if (e < N_EDGES) atomicAdd(&g_deg[dst[e]], 1);
}

__global__ void k_dinv() {
    int i = blockIdx.x * blockDim.x + threadIdx.x;
    if (i < N_NODES) g_dinv[i] = rsqrtf((float)g_deg[i] + 1.0f);
}

// ---------------- embedding lookup with max_norm=1 renorm ----------------
__global__ void k_embed(const int* __restrict__ x, const float* __restrict__ emb) {
    int t    = blockIdx.x * blockDim.x + threadIdx.x;
    int node = t >> 5;
    int lane = t & 31;
    if (node >= N_NODES) return;
    int v = __ldg(x + node);
    float4 e = __ldg((const float4*)(emb + (size_t)v * D) + lane);
    float ss = e.x * e.x + e.y * e.y + e.z * e.z + e.w * e.w;
    #pragma unroll
    for (int o = 16; o; o >>= 1) ss += __shfl_xor_sync(0xFFFFFFFFu, ss, o);
    float nrm   = sqrtf(ss);
    float scale = fminf(1.0f, 1.0f / fmaxf(nrm, 1e-7f));
    e.x *= scale; e.y *= scale; e.z *= scale; e.w *= scale;
    ((float4*)(g_h + (size_t)node * D))[lane] = e;
}

// ---------------- GEMM: hs = (g_h @ W) * dinv[row]; acc = 0 ----------------
// BM=128 rows per block, full N=128 cols, K=128 in chunks of 32.
__global__ __launch_bounds__(256) void k_gemm(const float* __restrict__ W) {
    __shared__ float As[128][32];
    __shared__ float Bs[32][128];

    int tid = threadIdx.x;
    int tx  = tid & 15;       // 16 col-groups of 8
    int ty  = tid >> 4;       // 16 row-groups of 8
    int rowBase = blockIdx.x * 128;

    float acc[8][8];
    #pragma unroll
    for (int i = 0; i < 8; i++)
        #pragma unroll
        for (int j = 0; j < 8; j++) acc[i][j] = 0.0f;

    for (int k0 = 0; k0 < D; k0 += 32) {
        // A tile: 128x32 floats = 1024 float4, 4 per thread
        #pragma unroll
        for (int i = 0; i < 4; i++) {
            int idx = tid + i * 256;
            int r   = idx >> 3;          // 8 float4 per row
            int c   = (idx & 7) << 2;
            int gr  = rowBase + r;
            float4 v = (gr < N_NODES)
                ? __ldg((const float4*)(g_h + (size_t)gr * D + k0 + c))
                : make_float4(0.f, 0.f, 0.f, 0.f);
            *(float4*)&As[r][c] = v;
        }
        // B tile: 32x128 floats = 1024 float4
        #pragma unroll
        for (int i = 0; i < 4; i++) {
            int idx = tid + i * 256;
            int r   = idx >> 5;          // 32 float4 per row
            int c   = (idx & 31) << 2;
            float4 v = __ldg((const float4*)(W + (size_t)(k0 + r) * D + c));
            *(float4*)&Bs[r][c] = v;
        }
        __syncthreads();

        #pragma unroll
        for (int k = 0; k < 32; k++) {
            float a[8], b[8];
            #pragma unroll
            for (int i = 0; i < 8; i++) a[i] = As[ty * 8 + i][k];
            float4 b0 = *(const float4*)&Bs[k][tx * 8];
            float4 b1 = *(const float4*)&Bs[k][tx * 8 + 4];
            b[0]=b0.x; b[1]=b0.y; b[2]=b0.z; b[3]=b0.w;
            b[4]=b1.x; b[5]=b1.y; b[6]=b1.z; b[7]=b1.w;
            #pragma unroll
            for (int i = 0; i < 8; i++)
                #pragma unroll
                for (int j = 0; j < 8; j++)
                    acc[i][j] = fmaf(a[i], b[j], acc[i][j]);
        }
        __syncthreads();
    }

    // epilogue: scale by dinv[row], write hs, zero acc
    #pragma unroll
    for (int i = 0; i < 8; i++) {
        int gr = rowBase + ty * 8 + i;
        if (gr < N_NODES) {
            float di = g_dinv[gr];
            float4 o0 = make_float4(acc[i][0]*di, acc[i][1]*di, acc[i][2]*di, acc[i][3]*di);
            float4 o1 = make_float4(acc[i][4]*di, acc[i][5]*di, acc[i][6]*di, acc[i][7]*di);
            size_t off = (size_t)gr * D + tx * 8;
            *(float4*)(g_hs + off)     = o0;
            *(float4*)(g_hs + off + 4) = o1;
            *(float4*)(g_acc + off)     = make_float4(0.f,0.f,0.f,0.f);
            *(float4*)(g_acc + off + 4) = make_float4(0.f,0.f,0.f,0.f);
        }
    }
}

// ---------------- edge scatter: acc[dst] += hs[src] (1 warp / edge) ----------------
__global__ void k_scatter(const int* __restrict__ src, const int* __restrict__ dst) {
    long long t = (long long)blockIdx.x * blockDim.x + threadIdx.x;
    int e = (int)(t >> 5);
    if (e >= N_EDGES) return;
    int lane = (int)(t & 31);
    int s = __ldg(src + e);
    int d = __ldg(dst + e);
    float4 v = __ldg((const float4*)(g_hs + (size_t)s * D) + lane);
    float* q = g_acc + (size_t)d * D + lane * 4;
    asm volatile("red.global.add.v4.f32 [%0], {%1, %2, %3, %4};"
                 :: "l"(__cvta_generic_to_global(q)),
                    "f"(v.x), "f"(v.y), "f"(v.z), "f"(v.w)
                 : "memory");
}

// ---------------- epilogue: h = relu((acc + hs) * dinv + b) ----------------
__global__ void k_epilogue(const float* __restrict__ b) {
    int idx = blockIdx.x * blockDim.x + threadIdx.x;   // over N_NODES*32 float4s
    if (idx >= N_NODES * 32) return;
    int node = idx >> 5;
    int c4   = idx & 31;
    float4 a = *(const float4*)(g_acc + (size_t)idx * 4);
    float4 s = *(const float4*)(g_hs  + (size_t)idx * 4);
    float  di = g_dinv[node];
    float4 bb = __ldg((const float4*)b + c4);
    float4 o;
    o.x = fmaxf((a.x + s.x) * di + bb.x, 0.0f);
    o.y = fmaxf((a.y + s.y) * di + bb.y, 0.0f);
    o.z = fmaxf((a.z + s.z) * di + bb.z, 0.0f);
    o.w = fmaxf((a.w + s.w) * di + bb.w, 0.0f);
    *(float4*)(g_h + (size_t)idx * 4) = o;
}

// ---------------- segment max over batch (values >= 0 post-ReLU) ----------------
__global__ void k_segmax(const int* __restrict__ batch) {
    int idx = blockIdx.x * blockDim.x + threadIdx.x;   // over N_NODES*32
    if (idx >= N_NODES * 32) return;
    int node = idx >> 5;
    int c4   = idx & 31;
    int bg = __ldg(batch + node);
    float4 v = *(const float4*)(g_h + (size_t)idx * 4);
    int* q = (int*)(g_gmax + (size_t)bg * D + c4 * 4);
    atomicMax(q + 0, __float_as_int(v.x));
    atomicMax(q + 1, __float_as_int(v.y));
    atomicMax(q + 2, __float_as_int(v.z));
    atomicMax(q + 3, __float_as_int(v.w));
}

// ---------------- final readout: out[g] = gmax[g] . Wf + bf ----------------
__global__ void k_final(const float* __restrict__ Wf, const float* __restrict__ bf,
                        float* __restrict__ out) {
    int t    = blockIdx.x * blockDim.x + threadIdx.x;
    int g    = t >> 5;
    int lane = t & 31;
    if (g >= N_GRAPHS) return;
    float4 v = *(const float4*)(g_gmax + (size_t)g * D + lane * 4);
    float4 w = __ldg((const float4*)Wf + lane);
    float s = v.x * w.x + v.y * w.y + v.z * w.z + v.w * w.w;
    #pragma unroll
    for (int o = 16; o; o >>= 1) s += __shfl_xor_sync(0xFFFFFFFFu, s, o);
    if (lane == 0) out[g] = s + bf[0];
}

// ---------------- launch ----------------
extern "C" void kernel_launch(void* const* d_in, const int* in_sizes, int n_in,
                              void* d_out, int out_size) {
    const int*   x     = (const int*)  d_in[0];
    const int*   ei    = (const int*)  d_in[1];
    const int*   batch = (const int*)  d_in[2];
    const float* emb   = (const float*)d_in[3];
    const float* Ws[3] = {(const float*)d_in[4], (const float*)d_in[6], (const float*)d_in[8]};
    const float* bs[3] = {(const float*)d_in[5], (const float*)d_in[7], (const float*)d_in[9]};
    const float* Wf    = (const float*)d_in[10];
    const float* bf    = (const float*)d_in[11];
    float* out = (float*)d_out;

    const int* src = ei;
    const int* dst = ei + N_EDGES;

    void* degPtr  = nullptr; cudaGetSymbolAddress(&degPtr,  g_deg);
    void* gmaxPtr = nullptr; cudaGetSymbolAddress(&gmaxPtr, g_gmax);
    cudaMemsetAsync(degPtr,  0, (size_t)N_NODES  * sizeof(int));
    cudaMemsetAsync(gmaxPtr, 0, (size_t)N_GRAPHS * D * sizeof(float));

    k_count_deg<<<(N_EDGES + 255) / 256, 256>>>(dst);
    k_dinv<<<(N_NODES + 255) / 256, 256>>>();
    k_embed<<<((size_t)N_NODES * 32 + 255) / 256, 256>>>(x, emb);

    for (int l = 0; l < 3; l++) {
        k_gemm<<<(N_NODES + 127) / 128, 256>>>(Ws[l]);
        k_scatter<<<(unsigned)(((long long)N_EDGES * 32 + 255) / 256), 256>>>(src, dst);
        k_epilogue<<<(N_NODES * 32 + 255) / 256, 256>>>(bs[l]);
    }

    k_segmax<<<(N_NODES * 32 + 255) / 256, 256>>>(batch);
    k_final<<<(N_GRAPHS * 32 + 255) / 256, 256>>>(Wf, bf, out);
}

// round 2
// speedup vs baseline: 1.4249x; 1.4249x over previous
#include <cuda_runtime.h>
#include <math.h>

#define N_NODES  100000
#define N_EDGES  1600000
#define N_GRAPHS 1000
#define D        128

// ---------------- scratch (static device globals; no allocation) ----------------
__device__ float g_h    [(size_t)N_NODES * D];   // current activations
__device__ float g_hs   [(size_t)N_NODES * D];   // (h @ W) * dinv[row]
__device__ float g_dinv [N_NODES];
__device__ int   g_deg  [N_NODES];
__device__ int   g_rowptr[N_NODES + 1];
__device__ int   g_cursor[N_NODES];
__device__ int   g_esrc [N_EDGES];               // src ids sorted by dst (CSR)
__device__ float g_gmax [N_GRAPHS * D];

// ---------------- degree count ----------------
__global__ void k_count_deg(const int* __restrict__ dst) {
    int e = blockIdx.x * blockDim.x + threadIdx.x;
    if (e < N_EDGES) atomicAdd(&g_deg[dst[e]], 1);
}

__global__ void k_dinv() {
    int i = blockIdx.x * blockDim.x + threadIdx.x;
    if (i < N_NODES) g_dinv[i] = rsqrtf((float)g_deg[i] + 1.0f);
}

// ---------------- single-block scan: rowptr / cursor from deg ----------------
__global__ void k_scan() {
    __shared__ int ssum[1024];
    int t = threadIdx.x;
    const int CH  = (N_NODES + 1023) / 1024;     // 98
    int beg = t * CH;
    int end = min(beg + CH, N_NODES);
    int s = 0;
    for (int i = beg; i < end; i++) s += g_deg[i];
    ssum[t] = s;
    __syncthreads();
    // Hillis-Steele inclusive scan over 1024 partials
    for (int off = 1; off < 1024; off <<= 1) {
        int v = (t >= off) ? ssum[t - off] : 0;
        __syncthreads();
        ssum[t] += v;
        __syncthreads();
    }
    int run = (t > 0) ? ssum[t - 1] : 0;
    for (int i = beg; i < end; i++) {
        g_rowptr[i] = run;
        g_cursor[i] = run;
        run += g_deg[i];
    }
    if (t == 0) g_rowptr[N_NODES] = N_EDGES;
}

// ---------------- CSR fill: bucket src ids by dst ----------------
__global__ void k_fill_csr(const int* __restrict__ src, const int* __restrict__ dst) {
    int e = blockIdx.x * blockDim.x + threadIdx.x;
    if (e >= N_EDGES) return;
    int d   = __ldg(dst + e);
    int pos = atomicAdd(&g_cursor[d], 1);
    g_esrc[pos] = __ldg(src + e);
}

// ---------------- embedding lookup with max_norm=1 renorm ----------------
__global__ void k_embed(const int* __restrict__ x, const float* __restrict__ emb) {
    int t    = blockIdx.x * blockDim.x + threadIdx.x;
    int node = t >> 5;
    int lane = t & 31;
    if (node >= N_NODES) return;
    int v = __ldg(x + node);
    float4 e = __ldg((const float4*)(emb + (size_t)v * D) + lane);
    float ss = e.x * e.x + e.y * e.y + e.z * e.z + e.w * e.w;
    #pragma unroll
    for (int o = 16; o; o >>= 1) ss += __shfl_xor_sync(0xFFFFFFFFu, ss, o);
    float nrm   = sqrtf(ss);
    float scale = fminf(1.0f, 1.0f / fmaxf(nrm, 1e-7f));
    e.x *= scale; e.y *= scale; e.z *= scale; e.w *= scale;
    ((float4*)(g_h + (size_t)node * D))[lane] = e;
}

// ---------------- GEMM: hs = (g_h @ W) * dinv[row] ----------------
__global__ __launch_bounds__(256) void k_gemm(const float* __restrict__ W) {
    __shared__ float As[128][32];
    __shared__ float Bs[32][128];

    int tid = threadIdx.x;
    int tx  = tid & 15;
    int ty  = tid >> 4;
    int rowBase = blockIdx.x * 128;

    float acc[8][8];
    #pragma unroll
    for (int i = 0; i < 8; i++)
        #pragma unroll
        for (int j = 0; j < 8; j++) acc[i][j] = 0.0f;

    for (int k0 = 0; k0 < D; k0 += 32) {
        #pragma unroll
        for (int i = 0; i < 4; i++) {
            int idx = tid + i * 256;
            int r   = idx >> 3;
            int c   = (idx & 7) << 2;
            int gr  = rowBase + r;
            float4 v = (gr < N_NODES)
                ? __ldg((const float4*)(g_h + (size_t)gr * D + k0 + c))
                : make_float4(0.f, 0.f, 0.f, 0.f);
            *(float4*)&As[r][c] = v;
        }
        #pragma unroll
        for (int i = 0; i < 4; i++) {
            int idx = tid + i * 256;
            int r   = idx >> 5;
            int c   = (idx & 31) << 2;
            float4 v = __ldg((const float4*)(W + (size_t)(k0 + r) * D + c));
            *(float4*)&Bs[r][c] = v;
        }
        __syncthreads();

        #pragma unroll
        for (int k = 0; k < 32; k++) {
            float a[8], b[8];
            #pragma unroll
            for (int i = 0; i < 8; i++) a[i] = As[ty * 8 + i][k];
            float4 b0 = *(const float4*)&Bs[k][tx * 8];
            float4 b1 = *(const float4*)&Bs[k][tx * 8 + 4];
            b[0]=b0.x; b[1]=b0.y; b[2]=b0.z; b[3]=b0.w;
            b[4]=b1.x; b[5]=b1.y; b[6]=b1.z; b[7]=b1.w;
            #pragma unroll
            for (int i = 0; i < 8; i++)
                #pragma unroll
                for (int j = 0; j < 8; j++)
                    acc[i][j] = fmaf(a[i], b[j], acc[i][j]);
        }
        __syncthreads();
    }

    #pragma unroll
    for (int i = 0; i < 8; i++) {
        int gr = rowBase + ty * 8 + i;
        if (gr < N_NODES) {
            float di = g_dinv[gr];
            float4 o0 = make_float4(acc[i][0]*di, acc[i][1]*di, acc[i][2]*di, acc[i][3]*di);
            float4 o1 = make_float4(acc[i][4]*di, acc[i][5]*di, acc[i][6]*di, acc[i][7]*di);
            size_t off = (size_t)gr * D + tx * 8;
            *(float4*)(g_hs + off)     = o0;
            *(float4*)(g_hs + off + 4) = o1;
        }
    }
}

// ---------------- CSR gather + fused epilogue (+ optional segmax) ----------------
// One warp per dst node: acc = sum over incoming edges of hs[src], then
// h = relu((acc + hs[n]) * dinv[n] + b). LAST layer scatters into segment max.
template<bool LAST>
__global__ void k_gather(const float* __restrict__ b, const int* __restrict__ batch) {
    int t    = blockIdx.x * blockDim.x + threadIdx.x;
    int n    = t >> 5;
    int lane = t & 31;
    if (n >= N_NODES) return;

    int beg = __ldg(&g_rowptr[n]);
    int end = __ldg(&g_rowptr[n + 1]);

    float4 a0 = make_float4(0.f,0.f,0.f,0.f);
    float4 a1 = a0, a2 = a0, a3 = a0;

    int e = beg;
    for (; e + 4 <= end; e += 4) {
        int s0 = __ldg(&g_esrc[e]);
        int s1 = __ldg(&g_esrc[e + 1]);
        int s2 = __ldg(&g_esrc[e + 2]);
        int s3 = __ldg(&g_esrc[e + 3]);
        float4 v0 = __ldg((const float4*)(g_hs + (size_t)s0 * D) + lane);
        float4 v1 = __ldg((const float4*)(g_hs + (size_t)s1 * D) + lane);
        float4 v2 = __ldg((const float4*)(g_hs + (size_t)s2 * D) + lane);
        float4 v3 = __ldg((const float4*)(g_hs + (size_t)s3 * D) + lane);
        a0.x += v0.x; a0.y += v0.y; a0.z += v0.z; a0.w += v0.w;
        a1.x += v1.x; a1.y += v1.y; a1.z += v1.z; a1.w += v1.w;
        a2.x += v2.x; a2.y += v2.y; a2.z += v2.z; a2.w += v2.w;
        a3.x += v3.x; a3.y += v3.y; a3.z += v3.z; a3.w += v3.w;
    }
    for (; e < end; e++) {
        int s = __ldg(&g_esrc[e]);
        float4 v = __ldg((const float4*)(g_hs + (size_t)s * D) + lane);
        a0.x += v.x; a0.y += v.y; a0.z += v.z; a0.w += v.w;
    }

    // self-loop term + combine partials
    float4 self = *((const float4*)(g_hs + (size_t)n * D) + lane);
    float4 acc;
    acc.x = (a0.x + a1.x) + (a2.x + a3.x) + self.x;
    acc.y = (a0.y + a1.y) + (a2.y + a3.y) + self.y;
    acc.z = (a0.z + a1.z) + (a2.z + a3.z) + self.z;
    acc.w = (a0.w + a1.w) + (a2.w + a3.w) + self.w;

    float  di = g_dinv[n];
    float4 bb = __ldg((const float4*)b + lane);
    float4 o;
    o.x = fmaxf(fmaf(acc.x, di, bb.x), 0.0f);
    o.y = fmaxf(fmaf(acc.y, di, bb.y), 0.0f);
    o.z = fmaxf(fmaf(acc.z, di, bb.z), 0.0f);
    o.w = fmaxf(fmaf(acc.w, di, bb.w), 0.0f);

    if (LAST) {
        int bg = __ldg(batch + n);
        int* q = (int*)(g_gmax + (size_t)bg * D + lane * 4);
        atomicMax(q + 0, __float_as_int(o.x));
        atomicMax(q + 1, __float_as_int(o.y));
        atomicMax(q + 2, __float_as_int(o.z));
        atomicMax(q + 3, __float_as_int(o.w));
    } else {
        *((float4*)(g_h + (size_t)n * D) + lane) = o;
    }
}

// ---------------- final readout: out[g] = gmax[g] . Wf + bf ----------------
__global__ void k_final(const float* __restrict__ Wf, const float* __restrict__ bf,
                        float* __restrict__ out) {
    int t    = blockIdx.x * blockDim.x + threadIdx.x;
    int g    = t >> 5;
    int lane = t & 31;
    if (g >= N_GRAPHS) return;
    float4 v = *((const float4*)(g_gmax + (size_t)g * D) + lane);
    float4 w = __ldg((const float4*)Wf + lane);
    float s = v.x * w.x + v.y * w.y + v.z * w.z + v.w * w.w;
    #pragma unroll
    for (int o = 16; o; o >>= 1) s += __shfl_xor_sync(0xFFFFFFFFu, s, o);
    if (lane == 0) out[g] = s + bf[0];
}

// ---------------- launch ----------------
extern "C" void kernel_launch(void* const* d_in, const int* in_sizes, int n_in,
                              void* d_out, int out_size) {
    const int*   x     = (const int*)  d_in[0];
    const int*   ei    = (const int*)  d_in[1];
    const int*   batch = (const int*)  d_in[2];
    const float* emb   = (const float*)d_in[3];
    const float* Ws[3] = {(const float*)d_in[4], (const float*)d_in[6], (const float*)d_in[8]};
    const float* bs[3] = {(const float*)d_in[5], (const float*)d_in[7], (const float*)d_in[9]};
    const float* Wf    = (const float*)d_in[10];
    const float* bf    = (const float*)d_in[11];
    float* out = (float*)d_out;

    const int* src = ei;
    const int* dst = ei + N_EDGES;

    void* degPtr  = nullptr; cudaGetSymbolAddress(&degPtr,  g_deg);
    void* gmaxPtr = nullptr; cudaGetSymbolAddress(&gmaxPtr, g_gmax);
    cudaMemsetAsync(degPtr,  0, (size_t)N_NODES  * sizeof(int));
    cudaMemsetAsync(gmaxPtr, 0, (size_t)N_GRAPHS * D * sizeof(float));

    k_count_deg<<<(N_EDGES + 255) / 256, 256>>>(dst);
    k_dinv<<<(N_NODES + 255) / 256, 256>>>();
    k_scan<<<1, 1024>>>();
    k_fill_csr<<<(N_EDGES + 255) / 256, 256>>>(src, dst);
    k_embed<<<((size_t)N_NODES * 32 + 255) / 256, 256>>>(x, emb);

    const int gatherGrid = (N_NODES * 32 + 255) / 256;
    for (int l = 0; l < 3; l++) {
        k_gemm<<<(N_NODES + 127) / 128, 256>>>(Ws[l]);
        if (l < 2) k_gather<false><<<gatherGrid, 256>>>(bs[l], batch);
        else       k_gather<true ><<<gatherGrid, 256>>>(bs[l], batch);
    }

    k_final<<<(N_GRAPHS * 32 + 255) / 256, 256>>>(Wf, bf, out);
}

// round 3
// speedup vs baseline: 1.6655x; 1.1688x over previous
#include <cuda_runtime.h>
#include <math.h>
#include <stdint.h>

#define N_NODES  100000
#define N_EDGES  1600000
#define N_GRAPHS 1000
#define D        128

// ---------------- scratch (static device globals; no allocation) ----------------
__device__ float g_h    [(size_t)N_NODES * D];   // current activations
__device__ float g_hs   [(size_t)N_NODES * D];   // (h @ W) * dinv[row]
__device__ float g_dinv [N_NODES];
__device__ int   g_deg  [N_NODES];
__device__ int   g_rowptr[N_NODES + 1];
__device__ int   g_cursor[N_NODES];
__device__ int   g_esrc [N_EDGES];               // src ids sorted by dst (CSR)
__device__ float g_gmax [N_GRAPHS * D];

// ---------------- degree count ----------------
__global__ void k_count_deg(const int* __restrict__ dst) {
    int e = blockIdx.x * blockDim.x + threadIdx.x;
    if (e < N_EDGES) atomicAdd(&g_deg[dst[e]], 1);
}

__global__ void k_dinv() {
    int i = blockIdx.x * blockDim.x + threadIdx.x;
    if (i < N_NODES) g_dinv[i] = rsqrtf((float)g_deg[i] + 1.0f);
}

// ---------------- single-block scan: rowptr / cursor from deg ----------------
__global__ void k_scan() {
    __shared__ int ssum[1024];
    int t = threadIdx.x;
    const int CH  = (N_NODES + 1023) / 1024;
    int beg = t * CH;
    int end = min(beg + CH, N_NODES);
    int s = 0;
    for (int i = beg; i < end; i++) s += g_deg[i];
    ssum[t] = s;
    __syncthreads();
    for (int off = 1; off < 1024; off <<= 1) {
        int v = (t >= off) ? ssum[t - off] : 0;
        __syncthreads();
        ssum[t] += v;
        __syncthreads();
    }
    int run = (t > 0) ? ssum[t - 1] : 0;
    for (int i = beg; i < end; i++) {
        g_rowptr[i] = run;
        g_cursor[i] = run;
        run += g_deg[i];
    }
    if (t == 0) g_rowptr[N_NODES] = N_EDGES;
}

// ---------------- CSR fill ----------------
__global__ void k_fill_csr(const int* __restrict__ src, const int* __restrict__ dst) {
    int e = blockIdx.x * blockDim.x + threadIdx.x;
    if (e >= N_EDGES) return;
    int d   = __ldg(dst + e);
    int pos = atomicAdd(&g_cursor[d], 1);
    g_esrc[pos] = __ldg(src + e);
}

// ---------------- embedding lookup with max_norm=1 renorm ----------------
__global__ void k_embed(const int* __restrict__ x, const float* __restrict__ emb) {
    int t    = blockIdx.x * blockDim.x + threadIdx.x;
    int node = t >> 5;
    int lane = t & 31;
    if (node >= N_NODES) return;
    int v = __ldg(x + node);
    float4 e = __ldg((const float4*)(emb + (size_t)v * D) + lane);
    float ss = e.x * e.x + e.y * e.y + e.z * e.z + e.w * e.w;
    #pragma unroll
    for (int o = 16; o; o >>= 1) ss += __shfl_xor_sync(0xFFFFFFFFu, ss, o);
    float nrm   = sqrtf(ss);
    float scale = fminf(1.0f, 1.0f / fmaxf(nrm, 1e-7f));
    e.x *= scale; e.y *= scale; e.z *= scale; e.w *= scale;
    ((float4*)(g_h + (size_t)node * D))[lane] = e;
}

// ---------------- TF32 helpers ----------------
__device__ __forceinline__ uint32_t f2tf32(float x) {
    uint32_t r;
    asm("cvt.rna.tf32.f32 %0, %1;" : "=r"(r) : "f"(x));
    return r;
}
__device__ __forceinline__ void split_tf32(float x, uint32_t& hi, uint32_t& lo) {
    hi = f2tf32(x);
    lo = f2tf32(x - __uint_as_float(hi));
}
__device__ __forceinline__ void mma_tf32(float* c, const uint32_t a0, const uint32_t a1,
                                         const uint32_t a2, const uint32_t a3,
                                         const uint32_t b0, const uint32_t b1) {
    asm volatile(
        "mma.sync.aligned.m16n8k8.row.col.f32.tf32.tf32.f32 "
        "{%0,%1,%2,%3}, {%4,%5,%6,%7}, {%8,%9}, {%0,%1,%2,%3};"
        : "+f"(c[0]), "+f"(c[1]), "+f"(c[2]), "+f"(c[3])
        : "r"(a0), "r"(a1), "r"(a2), "r"(a3), "r"(b0), "r"(b1));
}

// ---------------- GEMM (3xTF32): hs = (g_h @ W) * dinv[row] ----------------
// Block 128x128, 8 warps in 4(M)x2(N), warp tile 32x64, mma m16n8k8.
#define A_STRIDE 36
#define B_STRIDE 136
__global__ __launch_bounds__(256) void k_gemm(const float* __restrict__ W) {
    __shared__ float As[128][A_STRIDE];
    __shared__ float Bs[32][B_STRIDE];

    int tid  = threadIdx.x;
    int warp = tid >> 5, lane = tid & 31;
    int g = lane >> 2, t = lane & 3;
    int wm = warp >> 1;            // 0..3
    int wn = warp & 1;             // 0..1
    int rowBase = blockIdx.x * 128;
    int mBase = wm * 32;
    int nBase = wn * 64;

    float acc[2][8][4];
    #pragma unroll
    for (int i = 0; i < 2; i++)
        #pragma unroll
        for (int j = 0; j < 8; j++)
            #pragma unroll
            for (int k = 0; k < 4; k++) acc[i][j][k] = 0.0f;

    for (int k0 = 0; k0 < D; k0 += 32) {
        // stage A tile: 128x32
        #pragma unroll
        for (int i = 0; i < 4; i++) {
            int idx = tid + i * 256;
            int r   = idx >> 3;
            int c   = (idx & 7) << 2;
            int gr  = rowBase + r;
            float4 v = (gr < N_NODES)
                ? __ldg((const float4*)(g_h + (size_t)gr * D + k0 + c))
                : make_float4(0.f, 0.f, 0.f, 0.f);
            *(float4*)&As[r][c] = v;
        }
        // stage B tile: 32x128
        #pragma unroll
        for (int i = 0; i < 4; i++) {
            int idx = tid + i * 256;
            int r   = idx >> 5;
            int c   = (idx & 31) << 2;
            float4 v = __ldg((const float4*)(W + (size_t)(k0 + r) * D + c));
            *(float4*)&Bs[r][c] = v;
        }
        __syncthreads();

        #pragma unroll
        for (int ks = 0; ks < 32; ks += 8) {
            // A fragments for 2 m-tiles, hi/lo
            uint32_t ahi[2][4], alo[2][4];
            #pragma unroll
            for (int mt = 0; mt < 2; mt++) {
                int r0 = mBase + mt * 16 + g;
                int r1 = r0 + 8;
                float a0 = As[r0][ks + t];
                float a1 = As[r1][ks + t];
                float a2 = As[r0][ks + t + 4];
                float a3 = As[r1][ks + t + 4];
                split_tf32(a0, ahi[mt][0], alo[mt][0]);
                split_tf32(a1, ahi[mt][1], alo[mt][1]);
                split_tf32(a2, ahi[mt][2], alo[mt][2]);
                split_tf32(a3, ahi[mt][3], alo[mt][3]);
            }
            #pragma unroll
            for (int nt = 0; nt < 8; nt++) {
                int col = nBase + nt * 8 + g;
                float b0f = Bs[ks + t][col];
                float b1f = Bs[ks + t + 4][col];
                uint32_t bhi0, blo0, bhi1, blo1;
                split_tf32(b0f, bhi0, blo0);
                split_tf32(b1f, bhi1, blo1);
                #pragma unroll
                for (int mt = 0; mt < 2; mt++) {
                    mma_tf32(acc[mt][nt], alo[mt][0], alo[mt][1], alo[mt][2], alo[mt][3], bhi0, bhi1);
                    mma_tf32(acc[mt][nt], ahi[mt][0], ahi[mt][1], ahi[mt][2], ahi[mt][3], blo0, blo1);
                    mma_tf32(acc[mt][nt], ahi[mt][0], ahi[mt][1], ahi[mt][2], ahi[mt][3], bhi0, bhi1);
                }
            }
        }
        __syncthreads();
    }

    // epilogue: scale by dinv[row], write hs (float2 per fragment row)
    #pragma unroll
    for (int mt = 0; mt < 2; mt++) {
        int r0 = rowBase + mBase + mt * 16 + g;
        int r1 = r0 + 8;
        float d0 = (r0 < N_NODES) ? g_dinv[r0] : 0.0f;
        float d1 = (r1 < N_NODES) ? g_dinv[r1] : 0.0f;
        #pragma unroll
        for (int nt = 0; nt < 8; nt++) {
            int col = nBase + nt * 8 + 2 * t;
            if (r0 < N_NODES) {
                float2 v = make_float2(acc[mt][nt][0] * d0, acc[mt][nt][1] * d0);
                *(float2*)(g_hs + (size_t)r0 * D + col) = v;
            }
            if (r1 < N_NODES) {
                float2 v = make_float2(acc[mt][nt][2] * d1, acc[mt][nt][3] * d1);
                *(float2*)(g_hs + (size_t)r1 * D + col) = v;
            }
        }
    }
}

// ---------------- CSR gather + fused epilogue (+ optional segmax) ----------------
template<bool LAST>
__global__ void k_gather(const float* __restrict__ b, const int* __restrict__ batch) {
    int t    = blockIdx.x * blockDim.x + threadIdx.x;
    int n    = t >> 5;
    int lane = t & 31;
    if (n >= N_NODES) return;

    int beg = __ldg(&g_rowptr[n]);
    int end = __ldg(&g_rowptr[n + 1]);

    float4 a0 = make_float4(0.f,0.f,0.f,0.f);
    float4 a1 = a0, a2 = a0, a3 = a0;

    int e = beg;
    for (; e + 4 <= end; e += 4) {
        int s0 = __ldg(&g_esrc[e]);
        int s1 = __ldg(&g_esrc[e + 1]);
        int s2 = __ldg(&g_esrc[e + 2]);
        int s3 = __ldg(&g_esrc[e + 3]);
        float4 v0 = __ldg((const float4*)(g_hs + (size_t)s0 * D) + lane);
        float4 v1 = __ldg((const float4*)(g_hs + (size_t)s1 * D) + lane);
        float4 v2 = __ldg((const float4*)(g_hs + (size_t)s2 * D) + lane);
        float4 v3 = __ldg((const float4*)(g_hs + (size_t)s3 * D) + lane);
        a0.x += v0.x; a0.y += v0.y; a0.z += v0.z; a0.w += v0.w;
        a1.x += v1.x; a1.y += v1.y; a1.z += v1.z; a1.w += v1.w;
        a2.x += v2.x; a2.y += v2.y; a2.z += v2.z; a2.w += v2.w;
        a3.x += v3.x; a3.y += v3.y; a3.z += v3.z; a3.w += v3.w;
    }
    for (; e < end; e++) {
        int s = __ldg(&g_esrc[e]);
        float4 v = __ldg((const float4*)(g_hs + (size_t)s * D) + lane);
        a0.x += v.x; a0.y += v.y; a0.z += v.z; a0.w += v.w;
    }

    float4 self = *((const float4*)(g_hs + (size_t)n * D) + lane);
    float4 acc;
    acc.x = (a0.x + a1.x) + (a2.x + a3.x) + self.x;
    acc.y = (a0.y + a1.y) + (a2.y + a3.y) + self.y;
    acc.z = (a0.z + a1.z) + (a2.z + a3.z) + self.z;
    acc.w = (a0.w + a1.w) + (a2.w + a3.w) + self.w;

    float  di = g_dinv[n];
    float4 bb = __ldg((const float4*)b + lane);
    float4 o;
    o.x = fmaxf(fmaf(acc.x, di, bb.x), 0.0f);
    o.y = fmaxf(fmaf(acc.y, di, bb.y), 0.0f);
    o.z = fmaxf(fmaf(acc.z, di, bb.z), 0.0f);
    o.w = fmaxf(fmaf(acc.w, di, bb.w), 0.0f);

    if (LAST) {
        int bg = __ldg(batch + n);
        int* q = (int*)(g_gmax + (size_t)bg * D + lane * 4);
        atomicMax(q + 0, __float_as_int(o.x));
        atomicMax(q + 1, __float_as_int(o.y));
        atomicMax(q + 2, __float_as_int(o.z));
        atomicMax(q + 3, __float_as_int(o.w));
    } else {
        *((float4*)(g_h + (size_t)n * D) + lane) = o;
    }
}

// ---------------- final readout ----------------
__global__ void k_final(const float* __restrict__ Wf, const float* __restrict__ bf,
                        float* __restrict__ out) {
    int t    = blockIdx.x * blockDim.x + threadIdx.x;
    int g    = t >> 5;
    int lane = t & 31;
    if (g >= N_GRAPHS) return;
    float4 v = *((const float4*)(g_gmax + (size_t)g * D) + lane);
    float4 w = __ldg((const float4*)Wf + lane);
    float s = v.x * w.x + v.y * w.y + v.z * w.z + v.w * w.w;
    #pragma unroll
    for (int o = 16; o; o >>= 1) s += __shfl_xor_sync(0xFFFFFFFFu, s, o);
    if (lane == 0) out[g] = s + bf[0];
}

// ---------------- launch ----------------
extern "C" void kernel_launch(void* const* d_in, const int* in_sizes, int n_in,
                              void* d_out, int out_size) {
    const int*   x     = (const int*)  d_in[0];
    const int*   ei    = (const int*)  d_in[1];
    const int*   batch = (const int*)  d_in[2];
    const float* emb   = (const float*)d_in[3];
    const float* Ws[3] = {(const float*)d_in[4], (const float*)d_in[6], (const float*)d_in[8]};
    const float* bs[3] = {(const float*)d_in[5], (const float*)d_in[7], (const float*)d_in[9]};
    const float* Wf    = (const float*)d_in[10];
    const float* bf    = (const float*)d_in[11];
    float* out = (float*)d_out;

    const int* src = ei;
    const int* dst = ei + N_EDGES;

    void* degPtr  = nullptr; cudaGetSymbolAddress(&degPtr,  g_deg);
    void* gmaxPtr = nullptr; cudaGetSymbolAddress(&gmaxPtr, g_gmax);
    cudaMemsetAsync(degPtr,  0, (size_t)N_NODES  * sizeof(int));
    cudaMemsetAsync(gmaxPtr, 0, (size_t)N_GRAPHS * D * sizeof(float));

    k_count_deg<<<(N_EDGES + 255) / 256, 256>>>(dst);
    k_dinv<<<(N_NODES + 255) / 256, 256>>>();
    k_scan<<<1, 1024>>>();
    k_fill_csr<<<(N_EDGES + 255) / 256, 256>>>(src, dst);
    k_embed<<<((size_t)N_NODES * 32 + 255) / 256, 256>>>(x, emb);

    const int gatherGrid = (N_NODES * 32 + 255) / 256;
    for (int l = 0; l < 3; l++) {
        k_gemm<<<(N_NODES + 127) / 128, 256>>>(Ws[l]);
        if (l < 2) k_gather<false><<<gatherGrid, 256>>>(bs[l], batch);
        else       k_gather<true ><<<gatherGrid, 256>>>(bs[l], batch);
    }

    k_final<<<(N_GRAPHS * 32 + 255) / 256, 256>>>(Wf, bf, out);
}